// round 5
// baseline (speedup 1.0000x reference)
#include <cuda_runtime.h>
#include <cstdint>

#define NMAX 100000
#define EMAX 800000

typedef unsigned long long ULL;

// Scratch (static __device__ arrays per allocation rules)
__device__ float g_h[NMAX * 64];     // per-layer transformed features
__device__ float g_agg[NMAX * 64];   // layer-1 output (post relu)
__device__ float g_Wf[384 * 64];     // Wm @ W1 fused weight
__device__ float g_bf[64];           // bm @ W1 fused bias
__device__ float g_dinv[NMAX];
__device__ int   g_cnt[NMAX];
__device__ int   g_rowptr[NMAX];
__device__ int   g_pos[NMAX];
__device__ int   g_ssrc[EMAX];
__device__ float g_snorm[EMAX];
__device__ int   g_bsum[128];
__device__ int   g_bscan[128];

// ---------------- preprocessing ----------------

__global__ void k_init(int n) {
    int i = blockIdx.x * blockDim.x + threadIdx.x;
    if (i < n) { g_dinv[i] = 1.0f; g_cnt[i] = 0; }
}

__global__ void k_deg(const int* __restrict__ src, const int* __restrict__ dst,
                      const float* __restrict__ w, int e) {
    int i = blockIdx.x * blockDim.x + threadIdx.x;
    if (i < e) {
        int d = dst[i];
        atomicAdd(&g_dinv[d], w[i]);
        atomicAdd(&g_cnt[d], 1);
    }
}

__global__ void k_dinv(int n) {
    int i = blockIdx.x * blockDim.x + threadIdx.x;
    if (i < n) g_dinv[i] = rsqrtf(g_dinv[i]);
}

__global__ void k_scan1(int n) {
    __shared__ int sh[1024];
    int t = threadIdx.x;
    int i = blockIdx.x * 1024 + t;
    int v = (i < n) ? g_cnt[i] : 0;
    sh[t] = v; __syncthreads();
    #pragma unroll
    for (int off = 1; off < 1024; off <<= 1) {
        int x = (t >= off) ? sh[t - off] : 0;
        __syncthreads();
        sh[t] += x;
        __syncthreads();
    }
    if (i < n) g_rowptr[i] = sh[t] - v;
    if (t == 1023) g_bsum[blockIdx.x] = sh[1023];
}

__global__ void k_scan2(int nb) {
    __shared__ int sh[128];
    int t = threadIdx.x;
    int v = (t < nb) ? g_bsum[t] : 0;
    sh[t] = v; __syncthreads();
    #pragma unroll
    for (int off = 1; off < 128; off <<= 1) {
        int x = (t >= off) ? sh[t - off] : 0;
        __syncthreads();
        sh[t] += x;
        __syncthreads();
    }
    if (t < nb) g_bscan[t] = sh[t] - v;
}

__global__ void k_scan3(int n) {
    int i = blockIdx.x * blockDim.x + threadIdx.x;
    if (i < n) {
        int r = g_rowptr[i] + g_bscan[i >> 10];
        g_rowptr[i] = r;
        g_pos[i] = r;
    }
}

__global__ void k_fill(const int* __restrict__ src, const int* __restrict__ dst,
                       const float* __restrict__ w, int e) {
    int i = blockIdx.x * blockDim.x + threadIdx.x;
    if (i < e) {
        int d = dst[i], s = src[i];
        int p = atomicAdd(&g_pos[d], 1);
        g_ssrc[p] = s;
        g_snorm[p] = g_dinv[s] * w[i] * g_dinv[d];
    }
}

// ---------------- weight fusion ----------------

__global__ void k_fuseW(const float* __restrict__ Wm, const float* __restrict__ W1,
                        float* __restrict__ Wf) {
    int i = blockIdx.x * blockDim.x + threadIdx.x;
    if (i >= 384 * 64) return;
    int r = i >> 6, c = i & 63;
    float s = 0.f;
    #pragma unroll 8
    for (int k = 0; k < 64; k++) s += Wm[r * 64 + k] * W1[k * 64 + c];
    Wf[i] = s;
}

__global__ void k_fuseb(const float* __restrict__ bm, const float* __restrict__ W1,
                        float* __restrict__ bf) {
    int c = threadIdx.x;
    float s = 0.f;
    #pragma unroll 8
    for (int k = 0; k < 64; k++) s += bm[k] * W1[k * 64 + c];
    bf[c] = s;
}

// ---------------- FFMA2 GEMM: C[n,64] = A[n,K] @ W[K,64] (+bias) ----------
// BM=256, BN=64, BK=16, 256 threads.
// Per-thread tile: 8 rows (4 packed row-pairs) x 8 cols.
// All inner-loop operands are LDS.128 with zero packing MOVs:
//   - A transposed: LDS.128 = 4 consecutive rows = 2 packed row-pairs.
//   - B pre-duplicated 16B records (b,b,b',b'): LDS.128 = 2 packed b-pairs.
// Inner loop per kk: 6 LDS.128 + 32 FFMA2 (= 128 FMAs).

__device__ __forceinline__ void ffma2(ULL& d, ULL a, ULL b) {
    asm volatile("fma.rn.f32x2 %0, %1, %2, %0;" : "+l"(d) : "l"(a), "l"(b));
}

__device__ __forceinline__ float2 unpack2(ULL v) {
    float2 r;
    asm("mov.b64 {%0, %1}, %2;" : "=f"(r.x), "=f"(r.y) : "l"(v));
    return r;
}

__global__ __launch_bounds__(256)
void k_gemm(const float* __restrict__ A, const float* __restrict__ W,
            const float* __restrict__ bias, float* __restrict__ C,
            int n, int K) {
    __shared__ float As[16][260];    // transposed A tile (256 rows), padded
    __shared__ float Bs2[16][128];   // duplicated B: record (p&3)*8+(p>>2) has (b2p,b2p,b2p+1,b2p+1)
    int t = threadIdx.x;
    int rowBase = blockIdx.x * 256;
    int ty = t >> 3;          // 0..31 -> rows ty*8 .. ty*8+7
    int tx = t & 7;           // 0..7  -> cols tx*8 .. tx*8+7

    ULL acc[4][8];            // [row-pair][col]
    #pragma unroll
    for (int i = 0; i < 4; i++)
        #pragma unroll
        for (int j = 0; j < 8; j++) acc[i][j] = 0ull;

    for (int k0 = 0; k0 < K; k0 += 16) {
        // ---- load A tile (256 rows x 16 k), transposed into As[k][row] ----
        #pragma unroll
        for (int l = 0; l < 4; l++) {
            int lin = t + l * 256;          // 0..1023
            int r = lin >> 2;               // 0..255
            int c4 = (lin & 3) * 4;         // 0,4,8,12
            int row = rowBase + r;
            float4 v = make_float4(0.f, 0.f, 0.f, 0.f);
            if (row < n) v = *(const float4*)&A[(long)row * K + k0 + c4];
            As[c4 + 0][r] = v.x;
            As[c4 + 1][r] = v.y;
            As[c4 + 2][r] = v.z;
            As[c4 + 3][r] = v.w;
        }
        // ---- load B tile (16 x 64) into duplicated record layout ----
        {
            int kr = t >> 4;                // 0..15
            int q = t & 15;                 // 0..15 -> cols 4q..4q+3 (pairs p0=2q, p0+1)
            float4 v = *(const float4*)&W[(k0 + kr) * 64 + q * 4];
            int p0 = 2 * q, p1 = p0 + 1;
            int o0 = ((p0 & 3) * 8 + (p0 >> 2)) * 4;
            int o1 = ((p1 & 3) * 8 + (p1 >> 2)) * 4;
            *(float4*)&Bs2[kr][o0] = make_float4(v.x, v.x, v.y, v.y);
            *(float4*)&Bs2[kr][o1] = make_float4(v.z, v.z, v.w, v.w);
        }
        __syncthreads();
        #pragma unroll
        for (int kk = 0; kk < 16; kk++) {
            ulonglong2 a01 = *(const ulonglong2*)&As[kk][ty * 8];       // row-pairs 0,1
            ulonglong2 a23 = *(const ulonglong2*)&As[kk][ty * 8 + 4];   // row-pairs 2,3
            ULL av0 = a01.x, av1 = a01.y, av2 = a23.x, av3 = a23.y;
            #pragma unroll
            for (int j = 0; j < 4; j++) {
                // record (j*8+tx): cols (tx*8+2j) and (tx*8+2j+1), each duplicated
                ulonglong2 bv = *(const ulonglong2*)&Bs2[kk][(j * 8 + tx) * 4];
                ffma2(acc[0][2 * j], av0, bv.x); ffma2(acc[0][2 * j + 1], av0, bv.y);
                ffma2(acc[1][2 * j], av1, bv.x); ffma2(acc[1][2 * j + 1], av1, bv.y);
                ffma2(acc[2][2 * j], av2, bv.x); ffma2(acc[2][2 * j + 1], av2, bv.y);
                ffma2(acc[3][2 * j], av3, bv.x); ffma2(acc[3][2 * j + 1], av3, bv.y);
            }
        }
        __syncthreads();
    }

    float bv[8];
    #pragma unroll
    for (int j = 0; j < 8; j++) bv[j] = bias ? bias[tx * 8 + j] : 0.f;

    #pragma unroll
    for (int i = 0; i < 4; i++) {
        int row0 = rowBase + ty * 8 + 2 * i;
        float2 c[8];
        #pragma unroll
        for (int j = 0; j < 8; j++) c[j] = unpack2(acc[i][j]);
        if (row0 < n) {
            float4 o0 = make_float4(c[0].x + bv[0], c[1].x + bv[1], c[2].x + bv[2], c[3].x + bv[3]);
            float4 o1 = make_float4(c[4].x + bv[4], c[5].x + bv[5], c[6].x + bv[6], c[7].x + bv[7]);
            *(float4*)&C[(long)row0 * 64 + tx * 8] = o0;
            *(float4*)&C[(long)row0 * 64 + tx * 8 + 4] = o1;
        }
        if (row0 + 1 < n) {
            float4 o0 = make_float4(c[0].y + bv[0], c[1].y + bv[1], c[2].y + bv[2], c[3].y + bv[3]);
            float4 o1 = make_float4(c[4].y + bv[4], c[5].y + bv[5], c[6].y + bv[6], c[7].y + bv[7]);
            *(float4*)&C[(long)(row0 + 1) * 64 + tx * 8] = o0;
            *(float4*)&C[(long)(row0 + 1) * 64 + tx * 8 + 4] = o1;
        }
    }
}

// ---------------- aggregation: warp per node, float2 per lane ----------------

__global__ void k_agg(const float* __restrict__ h, float* __restrict__ out,
                      const float* __restrict__ bias, int n, int doRelu) {
    int warp = (blockIdx.x * blockDim.x + threadIdx.x) >> 5;
    int lane = threadIdx.x & 31;
    if (warp >= n) return;
    int start = g_rowptr[warp];
    int cnt = g_cnt[warp];
    const float2* hp = (const float2*)h;
    float ax = 0.f, ay = 0.f;
    for (int i = 0; i < cnt; i++) {
        int s = __ldg(&g_ssrc[start + i]);
        float nrm = __ldg(&g_snorm[start + i]);
        float2 v = hp[(long)s * 32 + lane];
        ax += v.x * nrm;
        ay += v.y * nrm;
    }
    float di = g_dinv[warp];
    float sn = di * di;
    float2 sv = hp[(long)warp * 32 + lane];
    ax += sv.x * sn;
    ay += sv.y * sn;
    ax += bias[lane * 2];
    ay += bias[lane * 2 + 1];
    if (doRelu) { ax = fmaxf(ax, 0.f); ay = fmaxf(ay, 0.f); }
    float2 o; o.x = ax; o.y = ay;
    ((float2*)out)[(long)warp * 32 + lane] = o;
}

// ---------------- launcher ----------------

extern "C" void kernel_launch(void* const* d_in, const int* in_sizes, int n_in,
                              void* d_out, int out_size) {
    const float* x  = (const float*)d_in[0];
    const int*   ei = (const int*)d_in[1];
    const float* w  = (const float*)d_in[2];
    const float* Wm = (const float*)d_in[3];
    const float* bm = (const float*)d_in[4];
    const float* W1 = (const float*)d_in[5];
    const float* b1 = (const float*)d_in[6];
    const float* W2 = (const float*)d_in[7];
    const float* b2 = (const float*)d_in[8];

    int e = in_sizes[2];
    int n = in_sizes[0] / 384;
    const int* src = ei;
    const int* dst = ei + e;

    void *p_h, *p_agg, *p_Wf, *p_bf;
    cudaGetSymbolAddress(&p_h,   g_h);
    cudaGetSymbolAddress(&p_agg, g_agg);
    cudaGetSymbolAddress(&p_Wf,  g_Wf);
    cudaGetSymbolAddress(&p_bf,  g_bf);
    float* h   = (float*)p_h;
    float* agg = (float*)p_agg;
    float* Wf  = (float*)p_Wf;
    float* bf  = (float*)p_bf;

    int nb = (n + 1023) / 1024;

    // fused layer-1 weights
    k_fuseW<<<(384 * 64 + 255) / 256, 256>>>(Wm, W1, Wf);
    k_fuseb<<<1, 64>>>(bm, W1, bf);

    // graph preprocessing (CSR + norms)
    k_init<<<(n + 255) / 256, 256>>>(n);
    k_deg<<<(e + 255) / 256, 256>>>(src, dst, w, e);
    k_dinv<<<(n + 255) / 256, 256>>>(n);
    k_scan1<<<nb, 1024>>>(n);
    k_scan2<<<1, 128>>>(nb);
    k_scan3<<<(n + 255) / 256, 256>>>(n);
    k_fill<<<(e + 255) / 256, 256>>>(src, dst, w, e);

    // layer 1 (fused): h = x @ Wf + bf ; agg = relu(aggregate(h) + b1)
    k_gemm<<<(n + 255) / 256, 256>>>(x, Wf, bf, h, n, 384);
    k_agg<<<(n + 7) / 8, 256>>>(h, agg, b1, n, 1);

    // layer 2: h = agg @ W2 ; out = aggregate(h) + b2
    k_gemm<<<(n + 255) / 256, 256>>>(agg, W2, nullptr, h, n, 64);
    k_agg<<<(n + 7) / 8, 256>>>(h, (float*)d_out, b2, n, 0);
}

// round 6
// speedup vs baseline: 1.2407x; 1.2407x over previous
#include <cuda_runtime.h>
#include <cstdint>

#define NMAX 100000
#define EMAX 800000

typedef unsigned long long ULL;

// Scratch (static __device__ arrays per allocation rules)
__device__ float g_h[NMAX * 64];     // per-layer transformed features
__device__ float g_agg[NMAX * 64];   // layer-1 output (post relu)
__device__ float g_Wf[384 * 64];     // Wm @ W1 fused weight
__device__ float g_bf[64];           // bm @ W1 fused bias
__device__ float g_dinv[NMAX];
__device__ int   g_cnt[NMAX];
__device__ int   g_rowptr[NMAX];
__device__ int   g_pos[NMAX];
__device__ int   g_ssrc[EMAX];
__device__ float g_snorm[EMAX];
__device__ int   g_bsum[128];
__device__ int   g_bscan[128];

// ---------------- preprocessing ----------------

__global__ void k_init(int n) {
    int i = blockIdx.x * blockDim.x + threadIdx.x;
    if (i < n) { g_dinv[i] = 1.0f; g_cnt[i] = 0; }
}

__global__ void k_deg(const int* __restrict__ src, const int* __restrict__ dst,
                      const float* __restrict__ w, int e) {
    int i = blockIdx.x * blockDim.x + threadIdx.x;
    if (i < e) {
        int d = dst[i];
        atomicAdd(&g_dinv[d], w[i]);
        atomicAdd(&g_cnt[d], 1);
    }
}

__global__ void k_dinv(int n) {
    int i = blockIdx.x * blockDim.x + threadIdx.x;
    if (i < n) g_dinv[i] = rsqrtf(g_dinv[i]);
}

__global__ void k_scan1(int n) {
    __shared__ int sh[1024];
    int t = threadIdx.x;
    int i = blockIdx.x * 1024 + t;
    int v = (i < n) ? g_cnt[i] : 0;
    sh[t] = v; __syncthreads();
    #pragma unroll
    for (int off = 1; off < 1024; off <<= 1) {
        int x = (t >= off) ? sh[t - off] : 0;
        __syncthreads();
        sh[t] += x;
        __syncthreads();
    }
    if (i < n) g_rowptr[i] = sh[t] - v;
    if (t == 1023) g_bsum[blockIdx.x] = sh[1023];
}

__global__ void k_scan2(int nb) {
    __shared__ int sh[128];
    int t = threadIdx.x;
    int v = (t < nb) ? g_bsum[t] : 0;
    sh[t] = v; __syncthreads();
    #pragma unroll
    for (int off = 1; off < 128; off <<= 1) {
        int x = (t >= off) ? sh[t - off] : 0;
        __syncthreads();
        sh[t] += x;
        __syncthreads();
    }
    if (t < nb) g_bscan[t] = sh[t] - v;
}

__global__ void k_scan3(int n) {
    int i = blockIdx.x * blockDim.x + threadIdx.x;
    if (i < n) {
        int r = g_rowptr[i] + g_bscan[i >> 10];
        g_rowptr[i] = r;
        g_pos[i] = r;
    }
}

__global__ void k_fill(const int* __restrict__ src, const int* __restrict__ dst,
                       const float* __restrict__ w, int e) {
    int i = blockIdx.x * blockDim.x + threadIdx.x;
    if (i < e) {
        int d = dst[i], s = src[i];
        int p = atomicAdd(&g_pos[d], 1);
        g_ssrc[p] = s;
        g_snorm[p] = g_dinv[s] * w[i] * g_dinv[d];
    }
}

// ---------------- weight fusion ----------------

__global__ void k_fuseW(const float* __restrict__ Wm, const float* __restrict__ W1,
                        float* __restrict__ Wf) {
    int i = blockIdx.x * blockDim.x + threadIdx.x;
    if (i >= 384 * 64) return;
    int r = i >> 6, c = i & 63;
    float s = 0.f;
    #pragma unroll 8
    for (int k = 0; k < 64; k++) s += Wm[r * 64 + k] * W1[k * 64 + c];
    Wf[i] = s;
}

__global__ void k_fuseb(const float* __restrict__ bm, const float* __restrict__ W1,
                        float* __restrict__ bf) {
    int c = threadIdx.x;
    float s = 0.f;
    #pragma unroll 8
    for (int k = 0; k < 64; k++) s += bm[k] * W1[k * 64 + c];
    bf[c] = s;
}

// ---------------- FFMA2 GEMM, double-buffered -----------------------------
// C[n,64] = A[n,K] @ W[K,64] (+bias). BM=128, BN=64, BK=16, 256 threads.
// Per-thread: 8 rows (4 packed row-pairs) x 4 cols. R3 layout (proven), plus
// double-buffered smem: next chunk's gmem loads issued before compute so
// DRAM latency overlaps the FFMA2 phase. One __syncthreads per chunk.

__device__ __forceinline__ void ffma2(ULL& d, ULL a, ULL b) {
    asm volatile("fma.rn.f32x2 %0, %1, %2, %0;" : "+l"(d) : "l"(a), "l"(b));
}

__device__ __forceinline__ ULL pack2(float v) {
    ULL r;
    asm("mov.b64 %0, {%1, %1};" : "=l"(r) : "f"(v));
    return r;
}

__device__ __forceinline__ float2 unpack2(ULL v) {
    float2 r;
    asm("mov.b64 {%0, %1}, %2;" : "=f"(r.x), "=f"(r.y) : "l"(v));
    return r;
}

__global__ __launch_bounds__(256)
void k_gemm(const float* __restrict__ A, const float* __restrict__ W,
            const float* __restrict__ bias, float* __restrict__ C,
            int n, int K) {
    __shared__ float As[2][16][132];   // transposed A tile, padded
    __shared__ float Bs[2][16][64];
    int t = threadIdx.x;
    int rowBase = blockIdx.x * 128;
    int ty = t >> 4;          // 0..15 -> 8 rows each (4 row-pairs)
    int tx = t & 15;          // 0..15 -> 4 cols each

    // loader mapping (A): thread covers rows r0,r0+... via 2 float4 loads
    int lr0 = t >> 1;                    // 0..127 (two threads per row? no:)
    // A tile loads: 512 float4 over 256 threads -> 2 each.
    // lin = t, t+256 ; r = lin>>2 ; c4 = (lin&3)*4
    int ar[2], ac[2];
    #pragma unroll
    for (int l = 0; l < 2; l++) {
        int lin = t + l * 256;
        ar[l] = lin >> 2;
        ac[l] = (lin & 3) * 4;
    }
    (void)lr0;
    int bkr = t >> 4;          // B loader: row kr, cols 4*(t&15)
    int bc  = (t & 15) * 4;

    ULL acc[4][4];
    #pragma unroll
    for (int i = 0; i < 4; i++)
        #pragma unroll
        for (int j = 0; j < 4; j++) acc[i][j] = 0ull;

    int nch = K >> 4;

    // prologue: load chunk 0 into buffer 0
    {
        #pragma unroll
        for (int l = 0; l < 2; l++) {
            int row = rowBase + ar[l];
            float4 v = make_float4(0.f, 0.f, 0.f, 0.f);
            if (row < n) v = *(const float4*)&A[(long)row * K + ac[l]];
            As[0][ac[l] + 0][ar[l]] = v.x;
            As[0][ac[l] + 1][ar[l]] = v.y;
            As[0][ac[l] + 2][ar[l]] = v.z;
            As[0][ac[l] + 3][ar[l]] = v.w;
        }
        *(float4*)&Bs[0][bkr][bc] = *(const float4*)&W[bkr * 64 + bc];
    }
    __syncthreads();

    for (int ch = 0; ch < nch; ch++) {
        int buf = ch & 1;
        // ---- issue next chunk's gmem loads first (latency overlaps compute) ----
        float4 pa[2];
        float4 pb;
        bool haveNext = (ch + 1) < nch;
        if (haveNext) {
            int k0 = (ch + 1) << 4;
            #pragma unroll
            for (int l = 0; l < 2; l++) {
                int row = rowBase + ar[l];
                pa[l] = make_float4(0.f, 0.f, 0.f, 0.f);
                if (row < n) pa[l] = *(const float4*)&A[(long)row * K + k0 + ac[l]];
            }
            pb = *(const float4*)&W[(k0 + bkr) * 64 + bc];
        }
        // ---- compute from current buffer ----
        #pragma unroll
        for (int kk = 0; kk < 16; kk++) {
            ULL a2[4];
            #pragma unroll
            for (int i = 0; i < 4; i++)
                a2[i] = *(const ULL*)&As[buf][kk][ty * 8 + 2 * i];
            float4 b4 = *(const float4*)&Bs[buf][kk][tx * 4];
            ULL bb[4];
            bb[0] = pack2(b4.x); bb[1] = pack2(b4.y);
            bb[2] = pack2(b4.z); bb[3] = pack2(b4.w);
            #pragma unroll
            for (int i = 0; i < 4; i++)
                #pragma unroll
                for (int j = 0; j < 4; j++)
                    ffma2(acc[i][j], a2[i], bb[j]);
        }
        // ---- store prefetched chunk to alternate buffer ----
        if (haveNext) {
            int nb2 = buf ^ 1;
            #pragma unroll
            for (int l = 0; l < 2; l++) {
                As[nb2][ac[l] + 0][ar[l]] = pa[l].x;
                As[nb2][ac[l] + 1][ar[l]] = pa[l].y;
                As[nb2][ac[l] + 2][ar[l]] = pa[l].z;
                As[nb2][ac[l] + 3][ar[l]] = pa[l].w;
            }
            *(float4*)&Bs[nb2][bkr][bc] = pb;
            __syncthreads();
        }
    }

    float bv[4];
    #pragma unroll
    for (int j = 0; j < 4; j++) bv[j] = bias ? bias[tx * 4 + j] : 0.f;

    #pragma unroll
    for (int i = 0; i < 4; i++) {
        int row0 = rowBase + ty * 8 + 2 * i;
        float2 c0 = unpack2(acc[i][0]);
        float2 c1 = unpack2(acc[i][1]);
        float2 c2 = unpack2(acc[i][2]);
        float2 c3 = unpack2(acc[i][3]);
        if (row0 < n) {
            float4 o = make_float4(c0.x + bv[0], c1.x + bv[1], c2.x + bv[2], c3.x + bv[3]);
            *(float4*)&C[(long)row0 * 64 + tx * 4] = o;
        }
        if (row0 + 1 < n) {
            float4 o = make_float4(c0.y + bv[0], c1.y + bv[1], c2.y + bv[2], c3.y + bv[3]);
            *(float4*)&C[(long)(row0 + 1) * 64 + tx * 4] = o;
        }
    }
}

// ---------------- aggregation: warp per node, float2 per lane ----------------

__global__ void k_agg(const float* __restrict__ h, float* __restrict__ out,
                      const float* __restrict__ bias, int n, int doRelu) {
    int warp = (blockIdx.x * blockDim.x + threadIdx.x) >> 5;
    int lane = threadIdx.x & 31;
    if (warp >= n) return;
    int start = g_rowptr[warp];
    int cnt = g_cnt[warp];
    const float2* hp = (const float2*)h;
    float ax = 0.f, ay = 0.f;
    for (int i = 0; i < cnt; i++) {
        int s = __ldg(&g_ssrc[start + i]);
        float nrm = __ldg(&g_snorm[start + i]);
        float2 v = hp[(long)s * 32 + lane];
        ax += v.x * nrm;
        ay += v.y * nrm;
    }
    float di = g_dinv[warp];
    float sn = di * di;
    float2 sv = hp[(long)warp * 32 + lane];
    ax += sv.x * sn;
    ay += sv.y * sn;
    ax += bias[lane * 2];
    ay += bias[lane * 2 + 1];
    if (doRelu) { ax = fmaxf(ax, 0.f); ay = fmaxf(ay, 0.f); }
    float2 o; o.x = ax; o.y = ay;
    ((float2*)out)[(long)warp * 32 + lane] = o;
}

// ---------------- launcher ----------------
// NOTE: launch order arranged so the big GEMM is launch index 5
// (ncu capture uses -s 5 -c 1; previous rounds kept profiling k_deg).

extern "C" void kernel_launch(void* const* d_in, const int* in_sizes, int n_in,
                              void* d_out, int out_size) {
    const float* x  = (const float*)d_in[0];
    const int*   ei = (const int*)d_in[1];
    const float* w  = (const float*)d_in[2];
    const float* Wm = (const float*)d_in[3];
    const float* bm = (const float*)d_in[4];
    const float* W1 = (const float*)d_in[5];
    const float* b1 = (const float*)d_in[6];
    const float* W2 = (const float*)d_in[7];
    const float* b2 = (const float*)d_in[8];

    int e = in_sizes[2];
    int n = in_sizes[0] / 384;
    const int* src = ei;
    const int* dst = ei + e;

    void *p_h, *p_agg, *p_Wf, *p_bf;
    cudaGetSymbolAddress(&p_h,   g_h);
    cudaGetSymbolAddress(&p_agg, g_agg);
    cudaGetSymbolAddress(&p_Wf,  g_Wf);
    cudaGetSymbolAddress(&p_bf,  g_bf);
    float* h   = (float*)p_h;
    float* agg = (float*)p_agg;
    float* Wf  = (float*)p_Wf;
    float* bf  = (float*)p_bf;

    int nb = (n + 1023) / 1024;

    // 0-2: degree accumulation (independent of weights)
    k_init<<<(n + 255) / 256, 256>>>(n);                       // launch 0
    k_deg<<<(e + 255) / 256, 256>>>(src, dst, w, e);           // launch 1
    k_dinv<<<(n + 255) / 256, 256>>>(n);                       // launch 2

    // 3-4: fused layer-1 weights
    k_fuseW<<<(384 * 64 + 255) / 256, 256>>>(Wm, W1, Wf);      // launch 3
    k_fuseb<<<1, 64>>>(bm, W1, bf);                            // launch 4

    // 5: layer 1 fused GEMM (profiled by ncu -s 5 -c 1)
    k_gemm<<<(n + 127) / 128, 256>>>(x, Wf, bf, h, n, 384);    // launch 5

    // 6-9: CSR build
    k_scan1<<<nb, 1024>>>(n);                                  // launch 6
    k_scan2<<<1, 128>>>(nb);                                   // launch 7
    k_scan3<<<(n + 255) / 256, 256>>>(n);                      // launch 8
    k_fill<<<(e + 255) / 256, 256>>>(src, dst, w, e);          // launch 9

    // layer 1 aggregate + relu
    k_agg<<<(n + 7) / 8, 256>>>(h, agg, b1, n, 1);             // launch 10

    // layer 2
    k_gemm<<<(n + 127) / 128, 256>>>(agg, W2, nullptr, h, n, 64);  // launch 11
    k_agg<<<(n + 7) / 8, 256>>>(h, (float*)d_out, b2, n, 0);       // launch 12
}